// round 17
// baseline (speedup 1.0000x reference)
#include <cuda_runtime.h>
#include <cuda_fp16.h>
#include <cstdint>
#include <math.h>

#define BB   16
#define DIM  384
#define NHKD 256
#define DHV  1024
#define NTOK 1024
#define NH   8
#define KDIM 32
#define DV   128

// packed fp16 buffers
__device__ uint2 g_xh2 [BB * 96 * NTOK];
__device__ uint2 g_xl2 [BB * 96 * NTOK];
__device__ uint2 g_xx2h[BB * 256 * NTOK];
__device__ uint2 g_xx2l[BB * 256 * NTOK];
__device__ uint2 g_qp2h[BB * 64 * NTOK], g_qp2l[BB * 64 * NTOK];
__device__ uint2 g_kp2h[BB * 64 * NTOK], g_kp2l[BB * 64 * NTOK];
__device__ uint32_t g_vp [BB * 1024 * 512];
// weights packed [m][kpair]
__device__ uint32_t g_wqh[256 * 192],  g_wql[256 * 192];
__device__ uint32_t g_wkh[256 * 192],  g_wkl[256 * 192];
__device__ uint32_t g_wvh[1024 * 192], g_wvl[1024 * 192];
__device__ uint32_t g_wph[384 * 512],  g_wpl[384 * 512];

__device__ __forceinline__ void mma16(float c[4], const uint32_t a[4],
                                      uint32_t b0, uint32_t b1) {
    asm volatile("mma.sync.aligned.m16n8k16.row.col.f32.f16.f16.f32 "
        "{%0,%1,%2,%3}, {%4,%5,%6,%7}, {%8,%9}, {%0,%1,%2,%3};"
        : "+f"(c[0]), "+f"(c[1]), "+f"(c[2]), "+f"(c[3])
        : "r"(a[0]), "r"(a[1]), "r"(a[2]), "r"(a[3]), "r"(b0), "r"(b1));
}
__device__ __forceinline__ void ldsm4(uint32_t r[4], const uint32_t* p) {
    uint32_t a = (uint32_t)__cvta_generic_to_shared(p);
    asm volatile("ldmatrix.sync.aligned.m8n8.x4.shared.b16 {%0,%1,%2,%3}, [%4];"
        : "=r"(r[0]), "=r"(r[1]), "=r"(r[2]), "=r"(r[3]) : "r"(a));
}
__device__ __forceinline__ void cpa16(void* dst, const void* src) {
    uint32_t a = (uint32_t)__cvta_generic_to_shared(dst);
    asm volatile("cp.async.cg.shared.global [%0], [%1], 16;" :: "r"(a), "l"(src));
}
#define CP_COMMIT() asm volatile("cp.async.commit_group;" ::: "memory")
#define CP_WAIT(n)  asm volatile("cp.async.wait_group %0;" :: "n"(n) : "memory")

__device__ __forceinline__ uint32_t pack2(float x0, float x1) {
    __half2 h = __floats2half2_rn(x0, x1);
    return *(uint32_t*)&h;
}
__device__ __forceinline__ void splitpack(float x0, float x1,
                                          uint32_t& h, uint32_t& l) {
    __half2 hh = __floats2half2_rn(x0, x1);
    float2 bk = __half22float2(hh);
    __half2 ll = __floats2half2_rn(x0 - bk.x, x1 - bk.y);
    h = *(uint32_t*)&hh;
    l = *(uint32_t*)&ll;
}
// deg-5 (accurate, for alpha / l)
__device__ __forceinline__ float fexp2(float z) {
    z = fmaxf(z, -100.0f);
    float zi = z + 12582912.0f;
    int   n  = __float_as_int(zi) - 0x4B400000;
    float t  = z - (zi - 12582912.0f);
    float p = fmaf(0.0013333558f, t, 0.0096181291f);
    p = fmaf(p, t, 0.0555041087f);
    p = fmaf(p, t, 0.2402265069f);
    p = fmaf(p, t, 0.6931471806f);
    p = fmaf(p, t, 1.0f);
    return __int_as_float(__float_as_int(p) + (n << 23));
}
// deg-4 (err ~4e-5, enough for fp16 P)
__device__ __forceinline__ float fexp2p(float z) {
    z = fmaxf(z, -100.0f);
    float zi = z + 12582912.0f;
    int   n  = __float_as_int(zi) - 0x4B400000;
    float t  = z - (zi - 12582912.0f);
    float p = fmaf(0.0096303680f, t, 0.0555046265f);
    p = fmaf(p, t, 0.2402264696f);
    p = fmaf(p, t, 0.6931471434f);
    p = fmaf(p, t, 1.0f);
    return __int_as_float(__float_as_int(p) + (n << 23));
}

// ---------------- prep kernels ----------------------------------------------
__global__ __launch_bounds__(256) void pack_w(
    const float* __restrict__ W, uint32_t* __restrict__ H,
    uint32_t* __restrict__ L, int M, int Kp)
{
    int idx = blockIdx.x * 256 + threadIdx.x;
    int m = idx / Kp, p = idx - m * Kp;
    float a = W[(long)m * (2 * Kp) + 2 * p];
    float b = W[(long)m * (2 * Kp) + 2 * p + 1];
    uint32_t hh, ll;
    splitpack(a, b, hh, ll);
    H[idx] = hh; L[idx] = ll;
}
__global__ __launch_bounds__(256) void pack_x(
    const float* __restrict__ X, uint2* __restrict__ H2,
    uint2* __restrict__ L2)
{
    int idx = blockIdx.x * 256 + threadIdx.x;
    int b = blockIdx.y;
    int gp = idx >> 10, n = idx & 1023;
    int c = gp >> 3, j = gp & 7, s = j >> 2, qq = j & 3;
    int k0 = 2 * (c * 16 + 8 * s + qq);
    const float* src = X + ((long)b * DIM + k0) * NTOK + n;
    uint32_t h0, l0, h1, l1;
    splitpack(src[0], src[NTOK], h0, l0);
    splitpack(src[8 * NTOK], src[9 * NTOK], h1, l1);
    long dst = ((long)b * 96 + gp) * NTOK + n;
    H2[dst] = make_uint2(h0, h1);
    L2[dst] = make_uint2(l0, l1);
}

// ============ fp16 3x-split GEMM + BN, cp.async 2-stage double buffer =======
// MODE 0: float output; MODE 1: V packed permuted; MODE 2: Q/K paired packed.
#define SW_H 0
#define SW_L 2560
#define SB_H 5120
#define SB_L 7232
#define GEMM_BUF_U32 9344
#define GEMM_SMEM_BYTES (2 * GEMM_BUF_U32 * 4)

template <int MODE>
__device__ __forceinline__ void gemm16_body(
    const uint32_t* __restrict__ WH, const uint32_t* __restrict__ WL,
    const uint2* __restrict__ XH2, const uint2* __restrict__ XL2,
    const float* __restrict__ bn, float* __restrict__ Yb,
    uint32_t* __restrict__ Vout, uint2* __restrict__ QHo,
    uint2* __restrict__ QLo, float qscale,
    int M, int Kp, int m0, int n0, uint32_t* smu)
{
    const int t = threadIdx.x, lane = t & 31, w = t >> 5;
    const int g = lane >> 2, q = lane & 3;
    const int mw = (w >> 2) * 64, nw = (w & 3) * 32;
    const int lrow = lane & 15, lsel = (lane >> 4) * 4;
    const int wrow = t >> 2, wquad = t & 3;
    const int pr = t >> 5, cq = t & 31;

    float c[4][4][4];
#pragma unroll
    for (int i = 0; i < 4; i++)
#pragma unroll
        for (int j = 0; j < 4; j++)
#pragma unroll
            for (int r = 0; r < 4; r++) c[i][j][r] = 0.f;

    const int nc = Kp >> 4;
    {
        uint32_t* base = smu;
#pragma unroll
        for (int i = 0; i < 2; i++) {
            int row = wrow + i * 64;
            cpa16(base + SW_H + row * 20 + wquad * 4,
                  WH + (long)(m0 + row) * Kp + wquad * 4);
            cpa16(base + SW_L + row * 20 + wquad * 4,
                  WL + (long)(m0 + row) * Kp + wquad * 4);
            int c2 = (cq + 32 * i) * 2;
            cpa16(base + SB_H + (pr * 132 + c2) * 2,
                  XH2 + (long)pr * NTOK + n0 + c2);
            cpa16(base + SB_L + (pr * 132 + c2) * 2,
                  XL2 + (long)pr * NTOK + n0 + c2);
        }
        CP_COMMIT();
    }

    for (int ch = 0; ch < nc; ch++) {
        if (ch + 1 < nc) {
            uint32_t* base = smu + ((ch + 1) & 1) * GEMM_BUF_U32;
            const int pc = (ch + 1) * 16, pg = (ch + 1) * 8;
#pragma unroll
            for (int i = 0; i < 2; i++) {
                int row = wrow + i * 64;
                cpa16(base + SW_H + row * 20 + wquad * 4,
                      WH + (long)(m0 + row) * Kp + pc + wquad * 4);
                cpa16(base + SW_L + row * 20 + wquad * 4,
                      WL + (long)(m0 + row) * Kp + pc + wquad * 4);
                int c2 = (cq + 32 * i) * 2;
                cpa16(base + SB_H + (pr * 132 + c2) * 2,
                      XH2 + (long)(pg + pr) * NTOK + n0 + c2);
                cpa16(base + SB_L + (pr * 132 + c2) * 2,
                      XL2 + (long)(pg + pr) * NTOK + n0 + c2);
            }
            CP_COMMIT();
            CP_WAIT(1);
        } else {
            CP_WAIT(0);
        }
        __syncthreads();

        uint32_t* base = smu + (ch & 1) * GEMM_BUF_U32;
        uint2* smBH = (uint2*)(base + SB_H);
        uint2* smBL = (uint2*)(base + SB_L);
#pragma unroll
        for (int ks = 0; ks < 2; ks++) {
            uint32_t ah[4][4], al[4][4];
#pragma unroll
            for (int mf = 0; mf < 4; mf++) {
                int ra = (mw + mf * 16 + lrow) * 20 + ks * 8 + lsel;
                ldsm4(ah[mf], base + SW_H + ra);
                ldsm4(al[mf], base + SW_L + ra);
            }
#pragma unroll
            for (int nf = 0; nf < 4; nf++) {
                int coln = nw + nf * 8 + g;
                uint2 bh = smBH[(4 * ks + q) * 132 + coln];
                uint2 bl = smBL[(4 * ks + q) * 132 + coln];
#pragma unroll
                for (int mf = 0; mf < 4; mf++) {
                    mma16(c[mf][nf], ah[mf], bh.x, bh.y);
                    mma16(c[mf][nf], ah[mf], bl.x, bl.y);
                    mma16(c[mf][nf], al[mf], bh.x, bh.y);
                }
            }
        }
        __syncthreads();
    }

#pragma unroll
    for (int mf = 0; mf < 4; mf++) {
        int r0 = m0 + mw + mf * 16 + g;
        int r1 = r0 + 8;
        float sc0 = bn[r0] * rsqrtf(bn[3 * M + r0] + 1e-5f);
        float tt0 = bn[M + r0] - bn[2 * M + r0] * sc0;
        float sc1 = bn[r1] * rsqrtf(bn[3 * M + r1] + 1e-5f);
        float tt1 = bn[M + r1] - bn[2 * M + r1] * sc1;
        if (MODE == 1) {
            uint32_t a0[4], a1[4];
#pragma unroll
            for (int nf = 0; nf < 4; nf++) {
                a0[nf] = pack2(c[mf][nf][0] * sc0 + tt0, c[mf][nf][1] * sc0 + tt0);
                a1[nf] = pack2(c[mf][nf][2] * sc1 + tt1, c[mf][nf][3] * sc1 + tt1);
            }
            int slot = (n0 >> 1) + ((nw & 64) ? 32 : 0) + q * 8 + ((nw & 32) >> 3);
            *(uint4*)(Vout + (long)r0 * 512 + slot) = make_uint4(a0[0], a0[1], a0[2], a0[3]);
            *(uint4*)(Vout + (long)r1 * 512 + slot) = make_uint4(a1[0], a1[1], a1[2], a1[3]);
        } else if (MODE == 2) {
            // paired Q/K pack: channel pairs (r0,r0+1)->x, (r0+8,r0+9)->y
            float s0 = sc0 * qscale, t0 = tt0 * qscale;
            float s1 = sc1 * qscale, t1 = tt1 * qscale;
            int gp = (r0 >> 5) * 8 + 4 * ((r0 >> 4) & 1) + (g >> 1);
#pragma unroll
            for (int nf = 0; nf < 4; nf++) {
                float v0 = c[mf][nf][0] * s0 + t0;
                float v1 = c[mf][nf][1] * s0 + t0;
                float v2 = c[mf][nf][2] * s1 + t1;
                float v3 = c[mf][nf][3] * s1 + t1;
                float n0v = __shfl_down_sync(0xffffffffu, v0, 4);
                float n1v = __shfl_down_sync(0xffffffffu, v1, 4);
                float n2v = __shfl_down_sync(0xffffffffu, v2, 4);
                float n3v = __shfl_down_sync(0xffffffffu, v3, 4);
                if ((lane & 4) == 0) {
                    int nn = n0 + nw + nf * 8 + 2 * q;
                    long basep = (long)gp * NTOK + nn;
                    uint32_t hx, lx, hy, ly;
                    splitpack(v0, n0v, hx, lx);
                    splitpack(v2, n2v, hy, ly);
                    QHo[basep] = make_uint2(hx, hy);
                    QLo[basep] = make_uint2(lx, ly);
                    splitpack(v1, n1v, hx, lx);
                    splitpack(v3, n3v, hy, ly);
                    QHo[basep + 1] = make_uint2(hx, hy);
                    QLo[basep + 1] = make_uint2(lx, ly);
                }
            }
        } else {
#pragma unroll
            for (int nf = 0; nf < 4; nf++) {
                int nn = n0 + nw + nf * 8 + 2 * q;
                float2 v0, v1;
                v0.x = c[mf][nf][0] * sc0 + tt0;
                v0.y = c[mf][nf][1] * sc0 + tt0;
                v1.x = c[mf][nf][2] * sc1 + tt1;
                v1.y = c[mf][nf][3] * sc1 + tt1;
                *(float2*)(Yb + (long)r0 * NTOK + nn) = v0;
                *(float2*)(Yb + (long)r1 * NTOK + nn) = v1;
            }
        }
    }
}

__global__ __launch_bounds__(256, 2) void gemm_qkv_tc(
    const float* __restrict__ bnq, const float* __restrict__ bnk,
    const float* __restrict__ bnv)
{
    extern __shared__ uint32_t smu[];
    const int y = blockIdx.y, b = blockIdx.z;
    const uint2* XH = g_xh2 + (long)b * 96 * NTOK;
    const uint2* XL = g_xl2 + (long)b * 96 * NTOK;
    if (y < 2) {
        gemm16_body<2>(g_wqh, g_wql, XH, XL, bnq, nullptr, nullptr,
                       g_qp2h + (long)b * 64 * NTOK, g_qp2l + (long)b * 64 * NTOK,
                       5.656854249492380f,
                       NHKD, 192, y * 128, blockIdx.x * 128, smu);
    } else if (y < 4) {
        gemm16_body<2>(g_wkh, g_wkl, XH, XL, bnk, nullptr, nullptr,
                       g_kp2h + (long)b * 64 * NTOK, g_kp2l + (long)b * 64 * NTOK,
                       1.0f,
                       NHKD, 192, (y - 2) * 128, blockIdx.x * 128, smu);
    } else {
        gemm16_body<1>(g_wvh, g_wvl, XH, XL, bnv, nullptr,
                       g_vp + (long)b * 1024 * 512, nullptr, nullptr, 1.0f,
                       DHV, 192, (y - 4) * 128, blockIdx.x * 128, smu);
    }
}

__global__ __launch_bounds__(256, 2) void gemm_proj_tc(
    const float* __restrict__ bnp, float* __restrict__ out)
{
    extern __shared__ uint32_t smu[];
    const int b = blockIdx.z;
    gemm16_body<0>(g_wph, g_wpl,
                   g_xx2h + (long)b * 256 * NTOK, g_xx2l + (long)b * 256 * NTOK,
                   bnp, out + (long)b * DIM * NTOK, nullptr, nullptr, nullptr,
                   1.0f, DIM, 512, blockIdx.y * 128, blockIdx.x * 128, smu);
}

// ---------------- FA2 attention, cp.async rotating prefetch -----------------
#define A_KH 0        // uint2 [8][132]
#define A_KL 2112
#define A_V0 4224     // u32 [128][36]
#define A_V1 8832
#define A_P  13440    // u32 [64][76]
#define A_MP 18304
#define A_SP 18432
#define A_MR 18560
#define A_LR 18688
#define ATTN_SMEM_U32 18752   // 75008 B

__global__ __launch_bounds__(256, 2) void attn_fa()
{
    extern __shared__ float sm[];
    uint32_t* smu = (uint32_t*)sm;
    uint2* smKH = (uint2*)(smu + A_KH);
    uint2* smKL = (uint2*)(smu + A_KL);
    const int t = threadIdx.x, lane = t & 31, w = t >> 5;
    const int mi = w >> 1, ni = w & 1;
    const int g = lane >> 2, q = lane & 3;
    const int q0 = blockIdx.x * 64;
    const int b = blockIdx.y >> 3, h = blockIdx.y & 7;
    const float L2E = 1.44269504088896f;

    const uint2* qp2h = g_qp2h + ((long)b * 64 + h * 8) * NTOK + q0;
    const uint2* qp2l = g_qp2l + ((long)b * 64 + h * 8) * NTOK + q0;
    const uint2* kp2h = g_kp2h + ((long)b * 64 + h * 8) * NTOK;
    const uint2* kp2l = g_kp2l + ((long)b * 64 + h * 8) * NTOK;
    const uint32_t* vpk = g_vp + ((long)b * 1024 + h * 128) * 512;

    const int pr = t >> 5, cq = t & 31;
    const int vd = t >> 1, hv = t & 1;

    if (t < 64) { sm[A_MR + t] = -1e30f; sm[A_MR + 64 + t] = -1e30f; sm[A_LR + t] = 0.f; }

    {
        long srow = (long)pr * NTOK;
#pragma unroll
        for (int i = 0; i < 2; i++) {
            int c2 = (cq + 32 * i) * 2;
            cpa16(smu + A_KH + (pr * 132 + c2) * 2, kp2h + srow + c2);
            cpa16(smu + A_KL + (pr * 132 + c2) * 2, kp2l + srow + c2);
        }
        const uint32_t* sv = vpk + (long)vd * 512 + hv * 16;
#pragma unroll
        for (int r = 0; r < 4; r++)
            cpa16(smu + A_V0 + vd * 36 + hv * 16 + r * 4, sv + r * 4);
        CP_COMMIT();
    }

    const int r0 = mi * 16 + g;
    uint32_t qh[2][4], ql[2][4];
#pragma unroll
    for (int s = 0; s < 2; s++) {
        long pi = (long)(4 * s + q) * NTOK;
        uint2 h0 = qp2h[pi + r0],  h1 = qp2h[pi + r0 + 8];
        uint2 l0 = qp2l[pi + r0],  l1 = qp2l[pi + r0 + 8];
        qh[s][0] = h0.x; qh[s][1] = h1.x; qh[s][2] = h0.y; qh[s][3] = h1.y;
        ql[s][0] = l0.x; ql[s][1] = l1.x; ql[s][2] = l0.y; ql[s][3] = l1.y;
    }

    float o[8][4];
#pragma unroll
    for (int nf = 0; nf < 8; nf++)
#pragma unroll
        for (int j = 0; j < 4; j++) o[nf][j] = 0.f;

    for (int it = 0; it < 8; it++) {
        CP_WAIT(0);
        __syncthreads();

        float s4[8][4];
#pragma unroll
        for (int nf = 0; nf < 8; nf++)
#pragma unroll
            for (int j = 0; j < 4; j++) s4[nf][j] = 0.f;
#pragma unroll
        for (int s = 0; s < 2; s++) {
#pragma unroll
            for (int nf = 0; nf < 8; nf++) {
                int col = ni * 64 + nf * 8 + g;
                uint2 bh = smKH[(4 * s + q) * 132 + col];
                uint2 bl = smKL[(4 * s + q) * 132 + col];
                mma16(s4[nf], qh[s], bh.x, bh.y);
                mma16(s4[nf], qh[s], bl.x, bl.y);
                mma16(s4[nf], ql[s], bh.x, bh.y);
            }
        }

        {
            float m0 = fmaxf(s4[0][0], s4[0][1]);
            float m1 = fmaxf(s4[0][2], s4[0][3]);
#pragma unroll
            for (int nf = 1; nf < 8; nf++) {
                m0 = fmaxf(m0, fmaxf(s4[nf][0], s4[nf][1]));
                m1 = fmaxf(m1, fmaxf(s4[nf][2], s4[nf][3]));
            }
            m0 = fmaxf(m0, __shfl_xor_sync(0xffffffffu, m0, 1));
            m0 = fmaxf(m0, __shfl_xor_sync(0xffffffffu, m0, 2));
            m1 = fmaxf(m1, __shfl_xor_sync(0xffffffffu, m1, 1));
            m1 = fmaxf(m1, __shfl_xor_sync(0xffffffffu, m1, 2));
            if (q == 0) {
                sm[A_MP + ni * 64 + r0] = m0;
                sm[A_MP + ni * 64 + r0 + 8] = m1;
            }
        }
        __syncthreads();

        {
            if (it < 7) {
                long srow = (long)pr * NTOK + (it + 1) * 128;
#pragma unroll
                for (int i = 0; i < 2; i++) {
                    int c2 = (cq + 32 * i) * 2;
                    cpa16(smu + A_KH + (pr * 132 + c2) * 2, kp2h + srow + c2);
                    cpa16(smu + A_KL + (pr * 132 + c2) * 2, kp2l + srow + c2);
                }
            }
            const uint32_t* sv = vpk + (long)vd * 512 + it * 64 + 32 + hv * 16;
#pragma unroll
            for (int r = 0; r < 4; r++)
                cpa16(smu + A_V1 + vd * 36 + hv * 16 + r * 4, sv + r * 4);
            CP_COMMIT();
        }

        {
            float moA = sm[A_MR + (it & 1) * 64 + r0];
            float moB = sm[A_MR + (it & 1) * 64 + r0 + 8];
            float mn0 = fmaxf(moA, fmaxf(sm[A_MP + r0], sm[A_MP + 64 + r0]));
            float mn1 = fmaxf(moB, fmaxf(sm[A_MP + r0 + 8], sm[A_MP + 64 + r0 + 8]));
            if (ni == 0 && q == 0) {
                sm[A_MR + ((it + 1) & 1) * 64 + r0] = mn0;
                sm[A_MR + ((it + 1) & 1) * 64 + r0 + 8] = mn1;
            }
            float al0 = fexp2((moA - mn0) * L2E);
            float al1 = fexp2((moB - mn1) * L2E);
            float c0 = -mn0 * L2E, c1 = -mn1 * L2E;
            float rs0 = 0.f, rs1 = 0.f;
            uint32_t p0v[8], p1v[8];
#pragma unroll
            for (int nf = 0; nf < 8; nf++) {
                float e00 = fexp2p(fmaf(s4[nf][0], L2E, c0));
                float e01 = fexp2p(fmaf(s4[nf][1], L2E, c0));
                float e10 = fexp2p(fmaf(s4[nf][2], L2E, c1));
                float e11 = fexp2p(fmaf(s4[nf][3], L2E, c1));
                rs0 += e00 + e01; rs1 += e10 + e11;
                p0v[nf] = pack2(e00, e01);
                p1v[nf] = pack2(e10, e11);
            }
            {
                uint32_t base = A_P + r0 * 76 + ni * 32 + q * 8;
                *(uint4*)(smu + base)     = make_uint4(p0v[0], p0v[1], p0v[2], p0v[3]);
                *(uint4*)(smu + base + 4) = make_uint4(p0v[4], p0v[5], p0v[6], p0v[7]);
                uint32_t base1 = A_P + (r0 + 8) * 76 + ni * 32 + q * 8;
                *(uint4*)(smu + base1)     = make_uint4(p1v[0], p1v[1], p1v[2], p1v[3]);
                *(uint4*)(smu + base1 + 4) = make_uint4(p1v[4], p1v[5], p1v[6], p1v[7]);
            }
            rs0 += __shfl_xor_sync(0xffffffffu, rs0, 1);
            rs0 += __shfl_xor_sync(0xffffffffu, rs0, 2);
            rs1 += __shfl_xor_sync(0xffffffffu, rs1, 1);
            rs1 += __shfl_xor_sync(0xffffffffu, rs1, 2);
            if (q == 0) {
                sm[A_SP + ni * 64 + r0] = rs0;
                sm[A_SP + ni * 64 + r0 + 8] = rs1;
            }
#pragma unroll
            for (int nf = 0; nf < 8; nf++) {
                o[nf][0] *= al0; o[nf][1] *= al0;
                o[nf][2] *= al1; o[nf][3] *= al1;
            }
        }
        __syncthreads();

        if (t < 64) {
            float mo = sm[A_MR + (it & 1) * 64 + t];
            float mn = sm[A_MR + ((it + 1) & 1) * 64 + t];
            sm[A_LR + t] = sm[A_LR + t] * fexp2((mo - mn) * L2E)
                         + sm[A_SP + t] + sm[A_SP + 64 + t];
        }

        {
            uint4 pa0 = *(const uint4*)(smu + A_P + r0 * 76 + q * 8);
            uint4 pa1 = *(const uint4*)(smu + A_P + r0 * 76 + q * 8 + 4);
            uint4 pb0 = *(const uint4*)(smu + A_P + (r0 + 8) * 76 + q * 8);
            uint4 pb1 = *(const uint4*)(smu + A_P + (r0 + 8) * 76 + q * 8 + 4);
            uint32_t pa[8] = {pa0.x, pa0.y, pa0.z, pa0.w, pa1.x, pa1.y, pa1.z, pa1.w};
            uint32_t pb[8] = {pb0.x, pb0.y, pb0.z, pb0.w, pb1.x, pb1.y, pb1.z, pb1.w};
            uint32_t as_[4][4];
#pragma unroll
            for (int s = 0; s < 4; s++) {
                as_[s][0] = pa[2 * s];     as_[s][1] = pb[2 * s];
                as_[s][2] = pa[2 * s + 1]; as_[s][3] = pb[2 * s + 1];
            }
#pragma unroll
            for (int nf = 0; nf < 8; nf++) {
                int d = ni * 64 + nf * 8 + g;
                uint4 v0 = *(const uint4*)(smu + A_V0 + d * 36 + q * 8);
                uint4 v1 = *(const uint4*)(smu + A_V0 + d * 36 + q * 8 + 4);
                uint32_t vv[8] = {v0.x, v0.y, v0.z, v0.w, v1.x, v1.y, v1.z, v1.w};
#pragma unroll
                for (int s = 0; s < 4; s++)
                    mma16(o[nf], as_[s], vv[2 * s], vv[2 * s + 1]);
            }
        }

        CP_WAIT(0);
        __syncthreads();

        if (it < 7) {
            const uint32_t* sv = vpk + (long)vd * 512 + (it + 1) * 64 + hv * 16;
#pragma unroll
            for (int r = 0; r < 4; r++)
                cpa16(smu + A_V0 + vd * 36 + hv * 16 + r * 4, sv + r * 4);
            CP_COMMIT();
        }

        {
            uint4 pa0 = *(const uint4*)(smu + A_P + r0 * 76 + 32 + q * 8);
            uint4 pa1 = *(const uint4*)(smu + A_P + r0 * 76 + 32 + q * 8 + 4);
            uint4 pb0 = *(const uint4*)(smu + A_P + (r0 + 8) * 76 + 32 + q * 8);
            uint4 pb1 = *(const uint4*)(smu + A_P + (r0 + 8) * 76 + 32 + q * 8 + 4);
            uint32_t pa[8] = {pa0.x, pa0.y, pa0.z, pa0.w, pa1.x, pa1.y, pa1.z, pa1.w};
            uint32_t pb[8] = {pb0.x, pb0.y, pb0.z, pb0.w, pb1.x, pb1.y, pb1.z, pb1.w};
            uint32_t as_[4][4];
#pragma unroll
            for (int s = 0; s < 4; s++) {
                as_[s][0] = pa[2 * s];     as_[s][1] = pb[2 * s];
                as_[s][2] = pa[2 * s + 1]; as_[s][3] = pb[2 * s + 1];
            }
#pragma unroll
            for (int nf = 0; nf < 8; nf++) {
                int d = ni * 64 + nf * 8 + g;
                uint4 v0 = *(const uint4*)(smu + A_V1 + d * 36 + q * 8);
                uint4 v1 = *(const uint4*)(smu + A_V1 + d * 36 + q * 8 + 4);
                uint32_t vv[8] = {v0.x, v0.y, v0.z, v0.w, v1.x, v1.y, v1.z, v1.w};
#pragma unroll
                for (int s = 0; s < 4; s++)
                    mma16(o[nf], as_[s], vv[2 * s], vv[2 * s + 1]);
            }
        }
    }

    __syncthreads();
    {
        float inv0 = 1.0f / sm[A_LR + r0];
        float inv1 = 1.0f / sm[A_LR + r0 + 8];
#pragma unroll
        for (int nf = 0; nf < 8; nf += 2) {
            int gpair = (h * 4 + ni * 2 + (nf >> 2)) * 8 + 4 * ((nf >> 1) & 1) + q;
            long base = ((long)b * 256 + gpair) * NTOK + q0;
            uint32_t hA0, lA0, hB0, lB0;
            uint32_t hA1, lA1, hB1, lB1;
            splitpack(o[nf][0] * inv0,     o[nf][1] * inv0,     hA0, lA0);
            splitpack(o[nf][2] * inv1,     o[nf][3] * inv1,     hB0, lB0);
            splitpack(o[nf + 1][0] * inv0, o[nf + 1][1] * inv0, hA1, lA1);
            splitpack(o[nf + 1][2] * inv1, o[nf + 1][3] * inv1, hB1, lB1);
            g_xx2h[base + r0]     = make_uint2(hA0, hA1);
            g_xx2l[base + r0]     = make_uint2(lA0, lA1);
            g_xx2h[base + r0 + 8] = make_uint2(hB0, hB1);
            g_xx2l[base + r0 + 8] = make_uint2(lB0, lB1);
        }
    }
}

// ---------------------------------------------------------------------------
extern "C" void kernel_launch(void* const* d_in, const int* in_sizes, int n_in,
                              void* d_out, int out_size)
{
    const float* x   = (const float*)d_in[0];
    const float* wq  = (const float*)d_in[1];
    const float* bnq = (const float*)d_in[2];
    const float* wk  = (const float*)d_in[3];
    const float* bnk = (const float*)d_in[4];
    const float* wv  = (const float*)d_in[5];
    const float* bnv = (const float*)d_in[6];
    const float* wp  = (const float*)d_in[7];
    const float* bnp = (const float*)d_in[8];
    float* out = (float*)d_out;

    uint32_t *wqh, *wql, *wkh, *wkl, *wvh, *wvl, *wph, *wpl;
    uint2 *xh2, *xl2;
    cudaGetSymbolAddress((void**)&wqh, g_wqh);
    cudaGetSymbolAddress((void**)&wql, g_wql);
    cudaGetSymbolAddress((void**)&wkh, g_wkh);
    cudaGetSymbolAddress((void**)&wkl, g_wkl);
    cudaGetSymbolAddress((void**)&wvh, g_wvh);
    cudaGetSymbolAddress((void**)&wvl, g_wvl);
    cudaGetSymbolAddress((void**)&wph, g_wph);
    cudaGetSymbolAddress((void**)&wpl, g_wpl);
    cudaGetSymbolAddress((void**)&xh2, g_xh2);
    cudaGetSymbolAddress((void**)&xl2, g_xl2);

    const int smem_attn = ATTN_SMEM_U32 * 4;   // 75008 B
    cudaFuncSetAttribute(attn_fa, cudaFuncAttributeMaxDynamicSharedMemorySize,
                         smem_attn);
    cudaFuncSetAttribute(gemm_qkv_tc, cudaFuncAttributeMaxDynamicSharedMemorySize,
                         GEMM_SMEM_BYTES);
    cudaFuncSetAttribute(gemm_proj_tc, cudaFuncAttributeMaxDynamicSharedMemorySize,
                         GEMM_SMEM_BYTES);
    dim3 blk(256);

    pack_w<<<192, blk>>>(wq, wqh, wql, NHKD, 192);
    pack_w<<<192, blk>>>(wk, wkh, wkl, NHKD, 192);
    pack_w<<<768, blk>>>(wv, wvh, wvl, DHV,  192);
    pack_w<<<768, blk>>>(wp, wph, wpl, DIM,  512);
    pack_x<<<dim3(384, BB), blk>>>(x, xh2, xl2);

    gemm_qkv_tc<<<dim3(8, 12, BB), blk, GEMM_SMEM_BYTES>>>(bnq, bnk, bnv);
    attn_fa<<<dim3(NTOK / 64, BB * NH), blk, smem_attn>>>();
    gemm_proj_tc<<<dim3(8, 3, BB), blk, GEMM_SMEM_BYTES>>>(bnp, out);
}